// round 13
// baseline (speedup 1.0000x reference)
#include <cuda_runtime.h>
#include <cstdint>

#define T_STEPS 2048
#define BATCH   32
#define DDIM    128
#define HDIM    256
#define MROWS   (T_STEPS*BATCH)   // 65536 rows, m = b*T + t
#define CHUNK   64
#define NCHUNK  (T_STEPS/CHUNK)   // 32
#define WARM    32

// Scratch (device globals: allocation-free rule)
__device__ float    g_u1[(size_t)MROWS * HDIM];        // GEMM1 out [m][H]
__device__ unsigned g_s1p[(size_t)MROWS * (HDIM/32)];  // LIF1 spikes packed [m][8]
__device__ float    g_u2[(size_t)MROWS * DDIM];        // GEMM2 out [m][D]
__device__ unsigned g_s2p[(size_t)MROWS * (DDIM/32)];  // LIF2 spikes packed [m][4]

// ================= helpers =================
__device__ __forceinline__ uint32_t cvt_tf32(float f) {
    uint32_t u;
    asm("cvt.rna.tf32.f32 %0, %1;" : "=r"(u) : "f"(f));
    return u;
}
// D += A*B, m16n8k8 tf32 (legacy mma.sync — supported on base compute_103)
__device__ __forceinline__ void mma8(float* c, const uint32_t* a, const uint32_t* b) {
    asm volatile(
        "mma.sync.aligned.m16n8k8.row.col.f32.tf32.tf32.f32 "
        "{%0,%1,%2,%3}, {%4,%5,%6,%7}, {%8,%9}, {%0,%1,%2,%3};"
        : "+f"(c[0]), "+f"(c[1]), "+f"(c[2]), "+f"(c[3])
        : "r"(a[0]), "r"(a[1]), "r"(a[2]), "r"(a[3]), "r"(b[0]), "r"(b[1]));
}

// ================= tf32-split NT GEMM via mma.sync =================
// C[m][n] = bias[n] + sum_k A[m][k]*B[n][k].
// Block 128x128, BK=32, 256 threads = 8 warps (2m x 4n), warp tile 64x32.
// fp32 tiles in smem; hi/lo tf32 split in registers at fragment-load time.
// PACKED_A: A is spike bitmask [m][K/32]; values {0,1} are tf32-exact.
// TERMS: 3 => aH*bH + aH*bL + aL*bH (fp32-equivalent); 2 => a*bH + a*bL.
template<int N_, int K_, bool PACKED_A, int TERMS>
__global__ void __launch_bounds__(256) gemm_mma(const void* __restrict__ Ain,
                                                const float* __restrict__ B,
                                                const float* __restrict__ bias,
                                                float* __restrict__ C)
{
    constexpr int BK = 32, NSTEP = K_ / BK, STR = 132;
    __shared__ float As[BK][STR];
    __shared__ float Bs[BK][STR];

    const int tid = threadIdx.x;
    const int wid = tid >> 5, lane = tid & 31;
    const int gid = lane >> 2, tig = lane & 3;
    const int wm = wid >> 2, wn = wid & 3;            // warps: 2 (m) x 4 (n)
    const int m0 = blockIdx.x * 128, n0 = blockIdx.y * 128;
    const int lr = tid >> 3;                          // 0..31 (load row base)
    const int lc = tid & 7;                           // 0..7  (k float4 group)

    const float*    Af = PACKED_A ? nullptr : (const float*)Ain;
    const unsigned* Ab = PACKED_A ? (const unsigned*)Ain : nullptr;

    float acc[4][4][4];
#pragma unroll
    for (int i = 0; i < 4; i++)
#pragma unroll
        for (int j = 0; j < 4; j++)
#pragma unroll
            for (int q = 0; q < 4; q++) acc[i][j][q] = 0.f;

    float4 pa[4], pb[4];
    unsigned paw = 0;

    auto fetch = [&](int s) {
        const int k0 = s * BK;
        if (PACKED_A) {
            if (tid < 128) paw = Ab[(size_t)(m0 + tid) * (K_ / 32) + s];
        } else {
#pragma unroll
            for (int i = 0; i < 4; i++)
                pa[i] = *reinterpret_cast<const float4*>(
                    Af + (size_t)(m0 + lr + i * 32) * K_ + k0 + lc * 4);
        }
#pragma unroll
        for (int i = 0; i < 4; i++)
            pb[i] = *reinterpret_cast<const float4*>(
                B + (size_t)(n0 + lr + i * 32) * K_ + k0 + lc * 4);
    };
    auto stash = [&]() {
        if (PACKED_A) {
            if (tid < 128) {
#pragma unroll
                for (int k = 0; k < 32; k++)
                    As[k][tid] = ((paw >> k) & 1u) ? 1.0f : 0.0f;
            }
        } else {
#pragma unroll
            for (int i = 0; i < 4; i++) {
                const float* v = reinterpret_cast<const float*>(&pa[i]);
#pragma unroll
                for (int j = 0; j < 4; j++) As[lc * 4 + j][lr + i * 32] = v[j];
            }
        }
#pragma unroll
        for (int i = 0; i < 4; i++) {
            const float* v = reinterpret_cast<const float*>(&pb[i]);
#pragma unroll
            for (int j = 0; j < 4; j++) Bs[lc * 4 + j][lr + i * 32] = v[j];
        }
    };

    fetch(0);
    for (int s = 0; s < NSTEP; s++) {
        __syncthreads();                 // prior compute done -> smem reusable
        stash();
        __syncthreads();                 // tile visible
        if (s + 1 < NSTEP) fetch(s + 1); // gmem loads overlap MMAs

#pragma unroll
        for (int c = 0; c < 4; c++) {    // 4 k-chunks of 8 within BK=32
            const int k0 = c * 8;
            // B fragments (hi/lo split in registers)
            uint32_t bh[4][2], bl[4][2];
#pragma unroll
            for (int nt = 0; nt < 4; nt++) {
                const float f0 = Bs[k0 + tig][wn * 32 + nt * 8 + gid];
                const float f1 = Bs[k0 + tig + 4][wn * 32 + nt * 8 + gid];
                bh[nt][0] = cvt_tf32(f0);
                bh[nt][1] = cvt_tf32(f1);
                bl[nt][0] = cvt_tf32(f0 - __uint_as_float(bh[nt][0]));
                bl[nt][1] = cvt_tf32(f1 - __uint_as_float(bh[nt][1]));
            }
            // A fragments + MMAs
#pragma unroll
            for (int mt = 0; mt < 4; mt++) {
                const int mb = wm * 64 + mt * 16 + gid;
                const float a0 = As[k0 + tig][mb];
                const float a1 = As[k0 + tig][mb + 8];
                const float a2 = As[k0 + tig + 4][mb];
                const float a3 = As[k0 + tig + 4][mb + 8];
                uint32_t ah[4], al[4];
                if (PACKED_A) {
                    ah[0] = __float_as_uint(a0); ah[1] = __float_as_uint(a1);
                    ah[2] = __float_as_uint(a2); ah[3] = __float_as_uint(a3);
                } else {
                    ah[0] = cvt_tf32(a0); ah[1] = cvt_tf32(a1);
                    ah[2] = cvt_tf32(a2); ah[3] = cvt_tf32(a3);
                    if (TERMS > 2) {
                        al[0] = cvt_tf32(a0 - __uint_as_float(ah[0]));
                        al[1] = cvt_tf32(a1 - __uint_as_float(ah[1]));
                        al[2] = cvt_tf32(a2 - __uint_as_float(ah[2]));
                        al[3] = cvt_tf32(a3 - __uint_as_float(ah[3]));
                    }
                }
#pragma unroll
                for (int nt = 0; nt < 4; nt++) {
                    mma8(acc[mt][nt], ah, bh[nt]);
                    mma8(acc[mt][nt], ah, bl[nt]);
                    if (TERMS > 2) mma8(acc[mt][nt], al, bh[nt]);
                }
            }
        }
    }

    // epilogue: add bias, write float2 per (c0,c1)/(c2,c3)
#pragma unroll
    for (int mt = 0; mt < 4; mt++) {
#pragma unroll
        for (int nt = 0; nt < 4; nt++) {
            const int row = m0 + wm * 64 + mt * 16 + gid;
            const int col = n0 + wn * 32 + nt * 8 + tig * 2;
            const float bx = bias[col], by = bias[col + 1];
            float2 v0 = make_float2(acc[mt][nt][0] + bx, acc[mt][nt][1] + by);
            float2 v1 = make_float2(acc[mt][nt][2] + bx, acc[mt][nt][3] + by);
            *reinterpret_cast<float2*>(C + (size_t)row * N_ + col)       = v0;
            *reinterpret_cast<float2*>(C + (size_t)(row + 8) * N_ + col) = v1;
        }
    }
}

// ================= time-parallel LIF1 (packed bitmask out) =================
// v' = fmaf(x - v, 0.5, v) contracts 2^-1/step; 32-step warm-up from v=0
// leaves state error < 6*2^-32 (flip prob ~0.01 over the whole tensor).
__global__ void __launch_bounds__(256) lif1_tp(const float* __restrict__ u,
                                               unsigned* __restrict__ spk)
{
    const int b = blockIdx.x, chunk = blockIdx.y;
    const int h = threadIdx.x;
    const int word = h >> 5, lane = h & 31;
    const int t0 = chunk * CHUNK;
    const int nwarm = chunk ? WARM : 0;
    const float* up = u + ((size_t)b * T_STEPS + (t0 - nwarm)) * HDIM + h;
    unsigned* wp = spk + ((size_t)b * T_STEPS + t0) * 8 + word;

    float v = 0.f;
    float bufA[16], bufB[16];
#pragma unroll
    for (int i = 0; i < 16; i++) bufA[i] = up[(size_t)i * HDIM];

    const int total = nwarm + CHUNK;
    for (int t = 0; t < total; t += 16) {
        const bool more = (t + 16) < total;
        if (more) {
#pragma unroll
            for (int i = 0; i < 16; i++) bufB[i] = up[(size_t)(t + 16 + i) * HDIM];
        }
#pragma unroll
        for (int i = 0; i < 16; i++) {
            const float hh = fmaf(bufA[i] - v, 0.5f, v);
            const bool fire = hh >= 1.0f;
            const int tt = t + i - nwarm;   // uniform across warp
            if (tt >= 0) {
                const unsigned m = __ballot_sync(0xffffffffu, fire);
                if (lane == 0) wp[(size_t)tt * 8] = m;
            }
            v = fire ? 0.0f : hh;
        }
        if (more) {
#pragma unroll
            for (int i = 0; i < 16; i++) bufA[i] = bufB[i];
        }
    }
}

// ================= time-parallel LIF2 (packed bitmask out) =================
__global__ void __launch_bounds__(128) lif2_tp(const float* __restrict__ u,
                                               unsigned* __restrict__ spk)
{
    const int b = blockIdx.x, chunk = blockIdx.y;
    const int d = threadIdx.x;
    const int word = d >> 5, lane = d & 31;
    const int t0 = chunk * CHUNK;
    const int nwarm = chunk ? WARM : 0;
    const float* up = u + ((size_t)b * T_STEPS + (t0 - nwarm)) * DDIM + d;
    unsigned* wp = spk + ((size_t)b * T_STEPS + t0) * 4 + word;

    float v = 0.f;
    float bufA[16], bufB[16];
#pragma unroll
    for (int i = 0; i < 16; i++) bufA[i] = up[(size_t)i * DDIM];

    const int total = nwarm + CHUNK;
    for (int t = 0; t < total; t += 16) {
        const bool more = (t + 16) < total;
        if (more) {
#pragma unroll
            for (int i = 0; i < 16; i++) bufB[i] = up[(size_t)(t + 16 + i) * DDIM];
        }
#pragma unroll
        for (int i = 0; i < 16; i++) {
            const float hh = fmaf(bufA[i] - v, 0.5f, v);
            const bool fire = hh >= 1.0f;
            const int tt = t + i - nwarm;
            if (tt >= 0) {
                const unsigned m = __ballot_sync(0xffffffffu, fire);
                if (lane == 0) wp[(size_t)tt * 4] = m;
            }
            v = fire ? 0.0f : hh;
        }
        if (more) {
#pragma unroll
            for (int i = 0; i < 16; i++) bufA[i] = bufB[i];
        }
    }
}

// ================= residual + LayerNorm (warp per row, D=128) =================
__global__ void __launch_bounds__(256) ln_kernel(const float* __restrict__ x,
                                                 const unsigned* __restrict__ spk,
                                                 const float* __restrict__ lnw,
                                                 const float* __restrict__ lnb,
                                                 float* __restrict__ out)
{
    const int row = blockIdx.x * 8 + (threadIdx.x >> 5);
    const int lane = threadIdx.x & 31;
    const float4 xv = *reinterpret_cast<const float4*>(x + (size_t)row * DDIM + lane * 4);
    const unsigned bits = spk[(size_t)row * 4 + (lane >> 3)];
    const int b0 = (lane & 7) * 4;
    float y0 = xv.x + (float)((bits >> (b0 + 0)) & 1u);
    float y1 = xv.y + (float)((bits >> (b0 + 1)) & 1u);
    float y2 = xv.z + (float)((bits >> (b0 + 2)) & 1u);
    float y3 = xv.w + (float)((bits >> (b0 + 3)) & 1u);
    float sum = y0 + y1 + y2 + y3;
    float sq  = y0 * y0 + y1 * y1 + y2 * y2 + y3 * y3;
#pragma unroll
    for (int o = 16; o > 0; o >>= 1) {
        sum += __shfl_xor_sync(0xffffffffu, sum, o);
        sq  += __shfl_xor_sync(0xffffffffu, sq,  o);
    }
    const float mu  = sum * (1.0f / 128.0f);
    const float var = sq * (1.0f / 128.0f) - mu * mu;
    const float inv = rsqrtf(var + 1e-5f);
    const float4 wv = *reinterpret_cast<const float4*>(lnw + lane * 4);
    const float4 bv = *reinterpret_cast<const float4*>(lnb + lane * 4);
    float4 ov;
    ov.x = (y0 - mu) * inv * wv.x + bv.x;
    ov.y = (y1 - mu) * inv * wv.y + bv.y;
    ov.z = (y2 - mu) * inv * wv.z + bv.z;
    ov.w = (y3 - mu) * inv * wv.w + bv.w;
    *reinterpret_cast<float4*>(out + (size_t)row * DDIM + lane * 4) = ov;
}

// ================= launch =================
extern "C" void kernel_launch(void* const* d_in, const int* in_sizes, int n_in,
                              void* d_out, int out_size)
{
    const float* x   = (const float*)d_in[0];
    const float* W1  = (const float*)d_in[1];
    const float* b1  = (const float*)d_in[2];
    const float* W2  = (const float*)d_in[3];
    const float* b2  = (const float*)d_in[4];
    const float* lnw = (const float*)d_in[5];
    const float* lnb = (const float*)d_in[6];
    float* out = (float*)d_out;

    float *u1, *u2;
    unsigned *s1p, *s2p;
    cudaGetSymbolAddress((void**)&u1,  g_u1);
    cudaGetSymbolAddress((void**)&s1p, g_s1p);
    cudaGetSymbolAddress((void**)&u2,  g_u2);
    cudaGetSymbolAddress((void**)&s2p, g_s2p);

    // GEMM1: u1 = x @ W1^T + b1   (tf32 3-term split ~ fp32 accuracy)
    gemm_mma<HDIM, DDIM, false, 3><<<dim3(MROWS / 128, HDIM / 128), 256>>>(x, W1, b1, u1);
    // LIF1: time-parallel scan (32 chunks of 64, 32-step warm-up), bit-packed spikes
    lif1_tp<<<dim3(BATCH, NCHUNK), 256>>>(u1, s1p);
    // GEMM2: u2 = s1 @ W2^T + b2  (spikes tf32-exact -> 2-term split)
    gemm_mma<DDIM, HDIM, true, 2><<<dim3(MROWS / 128, DDIM / 128), 256>>>(s1p, W2, b2, u2);
    // LIF2: time-parallel scan, bit-packed spikes
    lif2_tp<<<dim3(BATCH, NCHUNK), 128>>>(u2, s2p);
    // residual + LayerNorm
    ln_kernel<<<MROWS / 8, 256>>>(x, s2p, lnw, lnb, out);
}

// round 14
// speedup vs baseline: 1.0086x; 1.0086x over previous
#include <cuda_runtime.h>
#include <cstdint>

#define T_STEPS 2048
#define BATCH   32
#define DDIM    128
#define HDIM    256
#define MROWS   (T_STEPS*BATCH)   // 65536 rows, m = b*T + t
#define CHUNK   64
#define NCHUNK  (T_STEPS/CHUNK)   // 32
#define WARM    32

// Scratch (device globals: allocation-free rule)
__device__ float    g_u1[(size_t)MROWS * HDIM];        // GEMM1 out [m][H]
__device__ unsigned g_s1p[(size_t)MROWS * (HDIM/32)];  // LIF1 spikes packed [m][8]
__device__ float    g_u2[(size_t)MROWS * DDIM];        // GEMM2 out [m][D]
__device__ unsigned g_s2p[(size_t)MROWS * (DDIM/32)];  // LIF2 spikes packed [m][4]

// ================= helpers =================
__device__ __forceinline__ uint32_t cvt_tf32(float f) {
    uint32_t u;
    asm("cvt.rna.tf32.f32 %0, %1;" : "=r"(u) : "f"(f));
    return u;
}
// D += A*B, m16n8k8 tf32 (legacy mma.sync — supported on base compute_103)
__device__ __forceinline__ void mma8(float* c, const uint32_t* a, const uint32_t* b) {
    asm volatile(
        "mma.sync.aligned.m16n8k8.row.col.f32.tf32.tf32.f32 "
        "{%0,%1,%2,%3}, {%4,%5,%6,%7}, {%8,%9}, {%0,%1,%2,%3};"
        : "+f"(c[0]), "+f"(c[1]), "+f"(c[2]), "+f"(c[3])
        : "r"(a[0]), "r"(a[1]), "r"(a[2]), "r"(a[3]), "r"(b[0]), "r"(b[1]));
}

// ================= tf32-split NT GEMM via mma.sync =================
// C[m][n] = bias[n] + sum_k A[m][k]*B[n][k].
// Block 128x128, BK=32, 256 threads = 8 warps (2m x 4n), warp tile 64x32.
// fp32 tiles in smem; hi/lo tf32 split in registers at fragment-load time.
// PACKED_A: A is spike bitmask [m][K/32]; values {0,1} are tf32-exact.
// TERMS: 3 => aH*bH + aH*bL + aL*bH (fp32-equivalent); 2 => a*bH + a*bL.
template<int N_, int K_, bool PACKED_A, int TERMS>
__global__ void __launch_bounds__(256) gemm_mma(const void* __restrict__ Ain,
                                                const float* __restrict__ B,
                                                const float* __restrict__ bias,
                                                float* __restrict__ C)
{
    constexpr int BK = 32, NSTEP = K_ / BK, STR = 132;
    __shared__ float As[BK][STR];
    __shared__ float Bs[BK][STR];

    const int tid = threadIdx.x;
    const int wid = tid >> 5, lane = tid & 31;
    const int gid = lane >> 2, tig = lane & 3;
    const int wm = wid >> 2, wn = wid & 3;            // warps: 2 (m) x 4 (n)
    const int m0 = blockIdx.x * 128, n0 = blockIdx.y * 128;
    const int lr = tid >> 3;                          // 0..31 (load row base)
    const int lc = tid & 7;                           // 0..7  (k float4 group)

    const float*    Af = PACKED_A ? nullptr : (const float*)Ain;
    const unsigned* Ab = PACKED_A ? (const unsigned*)Ain : nullptr;

    float acc[4][4][4];
#pragma unroll
    for (int i = 0; i < 4; i++)
#pragma unroll
        for (int j = 0; j < 4; j++)
#pragma unroll
            for (int q = 0; q < 4; q++) acc[i][j][q] = 0.f;

    float4 pa[4], pb[4];
    unsigned paw = 0;

    auto fetch = [&](int s) {
        const int k0 = s * BK;
        if (PACKED_A) {
            if (tid < 128) paw = Ab[(size_t)(m0 + tid) * (K_ / 32) + s];
        } else {
#pragma unroll
            for (int i = 0; i < 4; i++)
                pa[i] = *reinterpret_cast<const float4*>(
                    Af + (size_t)(m0 + lr + i * 32) * K_ + k0 + lc * 4);
        }
#pragma unroll
        for (int i = 0; i < 4; i++)
            pb[i] = *reinterpret_cast<const float4*>(
                B + (size_t)(n0 + lr + i * 32) * K_ + k0 + lc * 4);
    };
    auto stash = [&]() {
        if (PACKED_A) {
            if (tid < 128) {
#pragma unroll
                for (int k = 0; k < 32; k++)
                    As[k][tid] = ((paw >> k) & 1u) ? 1.0f : 0.0f;
            }
        } else {
#pragma unroll
            for (int i = 0; i < 4; i++) {
                const float* v = reinterpret_cast<const float*>(&pa[i]);
#pragma unroll
                for (int j = 0; j < 4; j++) As[lc * 4 + j][lr + i * 32] = v[j];
            }
        }
#pragma unroll
        for (int i = 0; i < 4; i++) {
            const float* v = reinterpret_cast<const float*>(&pb[i]);
#pragma unroll
            for (int j = 0; j < 4; j++) Bs[lc * 4 + j][lr + i * 32] = v[j];
        }
    };

    fetch(0);
    for (int s = 0; s < NSTEP; s++) {
        __syncthreads();                 // prior compute done -> smem reusable
        stash();
        __syncthreads();                 // tile visible
        if (s + 1 < NSTEP) fetch(s + 1); // gmem loads overlap MMAs

#pragma unroll
        for (int c = 0; c < 4; c++) {    // 4 k-chunks of 8 within BK=32
            const int k0 = c * 8;
            // B fragments (hi/lo split in registers)
            uint32_t bh[4][2], bl[4][2];
#pragma unroll
            for (int nt = 0; nt < 4; nt++) {
                const float f0 = Bs[k0 + tig][wn * 32 + nt * 8 + gid];
                const float f1 = Bs[k0 + tig + 4][wn * 32 + nt * 8 + gid];
                bh[nt][0] = cvt_tf32(f0);
                bh[nt][1] = cvt_tf32(f1);
                bl[nt][0] = cvt_tf32(f0 - __uint_as_float(bh[nt][0]));
                bl[nt][1] = cvt_tf32(f1 - __uint_as_float(bh[nt][1]));
            }
            // A fragments + MMAs
#pragma unroll
            for (int mt = 0; mt < 4; mt++) {
                const int mb = wm * 64 + mt * 16 + gid;
                const float a0 = As[k0 + tig][mb];
                const float a1 = As[k0 + tig][mb + 8];
                const float a2 = As[k0 + tig + 4][mb];
                const float a3 = As[k0 + tig + 4][mb + 8];
                uint32_t ah[4], al[4];
                if (PACKED_A) {
                    ah[0] = __float_as_uint(a0); ah[1] = __float_as_uint(a1);
                    ah[2] = __float_as_uint(a2); ah[3] = __float_as_uint(a3);
                } else {
                    ah[0] = cvt_tf32(a0); ah[1] = cvt_tf32(a1);
                    ah[2] = cvt_tf32(a2); ah[3] = cvt_tf32(a3);
                    if (TERMS > 2) {
                        al[0] = cvt_tf32(a0 - __uint_as_float(ah[0]));
                        al[1] = cvt_tf32(a1 - __uint_as_float(ah[1]));
                        al[2] = cvt_tf32(a2 - __uint_as_float(ah[2]));
                        al[3] = cvt_tf32(a3 - __uint_as_float(ah[3]));
                    }
                }
#pragma unroll
                for (int nt = 0; nt < 4; nt++) {
                    mma8(acc[mt][nt], ah, bh[nt]);
                    mma8(acc[mt][nt], ah, bl[nt]);
                    if (TERMS > 2) mma8(acc[mt][nt], al, bh[nt]);
                }
            }
        }
    }

    // epilogue: add bias, write float2 per (c0,c1)/(c2,c3)
#pragma unroll
    for (int mt = 0; mt < 4; mt++) {
#pragma unroll
        for (int nt = 0; nt < 4; nt++) {
            const int row = m0 + wm * 64 + mt * 16 + gid;
            const int col = n0 + wn * 32 + nt * 8 + tig * 2;
            const float bx = bias[col], by = bias[col + 1];
            float2 v0 = make_float2(acc[mt][nt][0] + bx, acc[mt][nt][1] + by);
            float2 v1 = make_float2(acc[mt][nt][2] + bx, acc[mt][nt][3] + by);
            *reinterpret_cast<float2*>(C + (size_t)row * N_ + col)       = v0;
            *reinterpret_cast<float2*>(C + (size_t)(row + 8) * N_ + col) = v1;
        }
    }
}

// ================= time-parallel LIF1 (packed bitmask out) =================
// v' = fmaf(x - v, 0.5, v) contracts 2^-1/step; 32-step warm-up from v=0
// leaves state error < 6*2^-32 (flip prob ~0.01 over the whole tensor).
__global__ void __launch_bounds__(256) lif1_tp(const float* __restrict__ u,
                                               unsigned* __restrict__ spk)
{
    const int b = blockIdx.x, chunk = blockIdx.y;
    const int h = threadIdx.x;
    const int word = h >> 5, lane = h & 31;
    const int t0 = chunk * CHUNK;
    const int nwarm = chunk ? WARM : 0;
    const float* up = u + ((size_t)b * T_STEPS + (t0 - nwarm)) * HDIM + h;
    unsigned* wp = spk + ((size_t)b * T_STEPS + t0) * 8 + word;

    float v = 0.f;
    float bufA[16], bufB[16];
#pragma unroll
    for (int i = 0; i < 16; i++) bufA[i] = up[(size_t)i * HDIM];

    const int total = nwarm + CHUNK;
    for (int t = 0; t < total; t += 16) {
        const bool more = (t + 16) < total;
        if (more) {
#pragma unroll
            for (int i = 0; i < 16; i++) bufB[i] = up[(size_t)(t + 16 + i) * HDIM];
        }
#pragma unroll
        for (int i = 0; i < 16; i++) {
            const float hh = fmaf(bufA[i] - v, 0.5f, v);
            const bool fire = hh >= 1.0f;
            const int tt = t + i - nwarm;   // uniform across warp
            if (tt >= 0) {
                const unsigned m = __ballot_sync(0xffffffffu, fire);
                if (lane == 0) wp[(size_t)tt * 8] = m;
            }
            v = fire ? 0.0f : hh;
        }
        if (more) {
#pragma unroll
            for (int i = 0; i < 16; i++) bufA[i] = bufB[i];
        }
    }
}

// ================= time-parallel LIF2 (packed bitmask out) =================
__global__ void __launch_bounds__(128) lif2_tp(const float* __restrict__ u,
                                               unsigned* __restrict__ spk)
{
    const int b = blockIdx.x, chunk = blockIdx.y;
    const int d = threadIdx.x;
    const int word = d >> 5, lane = d & 31;
    const int t0 = chunk * CHUNK;
    const int nwarm = chunk ? WARM : 0;
    const float* up = u + ((size_t)b * T_STEPS + (t0 - nwarm)) * DDIM + d;
    unsigned* wp = spk + ((size_t)b * T_STEPS + t0) * 4 + word;

    float v = 0.f;
    float bufA[16], bufB[16];
#pragma unroll
    for (int i = 0; i < 16; i++) bufA[i] = up[(size_t)i * DDIM];

    const int total = nwarm + CHUNK;
    for (int t = 0; t < total; t += 16) {
        const bool more = (t + 16) < total;
        if (more) {
#pragma unroll
            for (int i = 0; i < 16; i++) bufB[i] = up[(size_t)(t + 16 + i) * DDIM];
        }
#pragma unroll
        for (int i = 0; i < 16; i++) {
            const float hh = fmaf(bufA[i] - v, 0.5f, v);
            const bool fire = hh >= 1.0f;
            const int tt = t + i - nwarm;
            if (tt >= 0) {
                const unsigned m = __ballot_sync(0xffffffffu, fire);
                if (lane == 0) wp[(size_t)tt * 4] = m;
            }
            v = fire ? 0.0f : hh;
        }
        if (more) {
#pragma unroll
            for (int i = 0; i < 16; i++) bufA[i] = bufB[i];
        }
    }
}

// ================= residual + LayerNorm (warp per row, D=128) =================
__global__ void __launch_bounds__(256) ln_kernel(const float* __restrict__ x,
                                                 const unsigned* __restrict__ spk,
                                                 const float* __restrict__ lnw,
                                                 const float* __restrict__ lnb,
                                                 float* __restrict__ out)
{
    const int row = blockIdx.x * 8 + (threadIdx.x >> 5);
    const int lane = threadIdx.x & 31;
    const float4 xv = *reinterpret_cast<const float4*>(x + (size_t)row * DDIM + lane * 4);
    const unsigned bits = spk[(size_t)row * 4 + (lane >> 3)];
    const int b0 = (lane & 7) * 4;
    float y0 = xv.x + (float)((bits >> (b0 + 0)) & 1u);
    float y1 = xv.y + (float)((bits >> (b0 + 1)) & 1u);
    float y2 = xv.z + (float)((bits >> (b0 + 2)) & 1u);
    float y3 = xv.w + (float)((bits >> (b0 + 3)) & 1u);
    float sum = y0 + y1 + y2 + y3;
    float sq  = y0 * y0 + y1 * y1 + y2 * y2 + y3 * y3;
#pragma unroll
    for (int o = 16; o > 0; o >>= 1) {
        sum += __shfl_xor_sync(0xffffffffu, sum, o);
        sq  += __shfl_xor_sync(0xffffffffu, sq,  o);
    }
    const float mu  = sum * (1.0f / 128.0f);
    const float var = sq * (1.0f / 128.0f) - mu * mu;
    const float inv = rsqrtf(var + 1e-5f);
    const float4 wv = *reinterpret_cast<const float4*>(lnw + lane * 4);
    const float4 bv = *reinterpret_cast<const float4*>(lnb + lane * 4);
    float4 ov;
    ov.x = (y0 - mu) * inv * wv.x + bv.x;
    ov.y = (y1 - mu) * inv * wv.y + bv.y;
    ov.z = (y2 - mu) * inv * wv.z + bv.z;
    ov.w = (y3 - mu) * inv * wv.w + bv.w;
    *reinterpret_cast<float4*>(out + (size_t)row * DDIM + lane * 4) = ov;
}

// ================= launch =================
extern "C" void kernel_launch(void* const* d_in, const int* in_sizes, int n_in,
                              void* d_out, int out_size)
{
    const float* x   = (const float*)d_in[0];
    const float* W1  = (const float*)d_in[1];
    const float* b1  = (const float*)d_in[2];
    const float* W2  = (const float*)d_in[3];
    const float* b2  = (const float*)d_in[4];
    const float* lnw = (const float*)d_in[5];
    const float* lnb = (const float*)d_in[6];
    float* out = (float*)d_out;

    float *u1, *u2;
    unsigned *s1p, *s2p;
    cudaGetSymbolAddress((void**)&u1,  g_u1);
    cudaGetSymbolAddress((void**)&s1p, g_s1p);
    cudaGetSymbolAddress((void**)&u2,  g_u2);
    cudaGetSymbolAddress((void**)&s2p, g_s2p);

    // GEMM1: u1 = x @ W1^T + b1   (tf32 3-term split ~ fp32 accuracy)
    gemm_mma<HDIM, DDIM, false, 3><<<dim3(MROWS / 128, HDIM / 128), 256>>>(x, W1, b1, u1);
    // LIF1: time-parallel scan (32 chunks of 64, 32-step warm-up), bit-packed spikes
    lif1_tp<<<dim3(BATCH, NCHUNK), 256>>>(u1, s1p);
    // GEMM2: u2 = s1 @ W2^T + b2  (spikes tf32-exact -> 2-term split)
    gemm_mma<DDIM, HDIM, true, 2><<<dim3(MROWS / 128, DDIM / 128), 256>>>(s1p, W2, b2, u2);
    // LIF2: time-parallel scan, bit-packed spikes
    lif2_tp<<<dim3(BATCH, NCHUNK), 128>>>(u2, s2p);
    // residual + LayerNorm
    ln_kernel<<<MROWS / 8, 256>>>(x, s2p, lnw, lnb, out);
}